// round 10
// baseline (speedup 1.0000x reference)
#include <cuda_runtime.h>
#include <cuda_bf16.h>
#include <math.h>

#define BATCH 4
#define SPAST 1024
#define SFUT 512
#define NTOK 1536
#define DM 256
#define NH 8
#define DH 32
#define DFF 2048
#define NLAYERS 8
#define NROWS (BATCH*NTOK)        // 6144
#define CHUNK 128
#define NCHUNK (NTOK/CHUNK)       // 12
#define NBH (BATCH*NH)            // 32

typedef unsigned long long ull;
typedef __nv_bfloat16 bf16;
typedef __nv_bfloat162 bf162;

// ---------------- scratch (no allocation allowed) ----------------
__device__ float g_x  [NROWS*DM];
__device__ float g_qb [NROWS*DM];
__device__ float g_kb [NROWS*DM];
__device__ float g_vb [NROWS*DM];
__device__ float g_part[4*NROWS*DM];
__device__ float g_Sloc[NBH*NCHUNK*DH*DH];
__device__ float g_kloc[NBH*NCHUNK*DH];

__device__ bf16 g_xh[NROWS*DM],  g_xl[NROWS*DM];
__device__ bf16 g_ah[NROWS*DM],  g_al[NROWS*DM];
__device__ bf16 g_hh[NROWS*DFF], g_hl[NROWS*DFF];
// transposed K-major weights, hi/lo split: [L][N][K]
__device__ bf16 g_wqh[NLAYERS*DM*DM],  g_wql[NLAYERS*DM*DM];
__device__ bf16 g_wkh[NLAYERS*DM*DM],  g_wkl[NLAYERS*DM*DM];
__device__ bf16 g_wvh[NLAYERS*DM*DM],  g_wvl[NLAYERS*DM*DM];
__device__ bf16 g_woh[NLAYERS*DM*DM],  g_wol[NLAYERS*DM*DM];
__device__ bf16 g_w1h[NLAYERS*DM*DFF], g_w1l[NLAYERS*DM*DFF];
__device__ bf16 g_w2h[NLAYERS*DFF*DM], g_w2l[NLAYERS*DFF*DM];

// ---------------- helpers ----------------
__device__ __forceinline__ unsigned smem_u32(const void* p){
    return (unsigned)__cvta_generic_to_shared(p);
}
__device__ __forceinline__ void ldsm_x4(unsigned* r, unsigned addr){
    asm volatile("ldmatrix.sync.aligned.m8n8.x4.shared.b16 {%0,%1,%2,%3}, [%4];"
        : "=r"(r[0]), "=r"(r[1]), "=r"(r[2]), "=r"(r[3]) : "r"(addr));
}
__device__ __forceinline__ void mma16816(float* c, const unsigned* a, const unsigned* b){
    asm volatile("mma.sync.aligned.m16n8k16.row.col.f32.bf16.bf16.f32 "
        "{%0,%1,%2,%3}, {%4,%5,%6,%7}, {%8,%9}, {%0,%1,%2,%3};"
        : "+f"(c[0]), "+f"(c[1]), "+f"(c[2]), "+f"(c[3])
        : "r"(a[0]), "r"(a[1]), "r"(a[2]), "r"(a[3]), "r"(b[0]), "r"(b[1]));
}
__device__ __forceinline__ void split_bf16(float v, bf16& h, bf16& l){
    h = __float2bfloat16(v);
    l = __float2bfloat16(v - __bfloat162float(h));
}

// ---------------- fused weight transpose + bf16 split (ONE launch) ----------------
struct ConvArgs {
    const float* W[6];
    bf16* Oh[6];
    bf16* Ol[6];
};
#define CONV_BLOCKS (2048 + 4096 + 4096)

__global__ void convw_all(ConvArgs a)
{
    __shared__ float s[32][33];
    int bid = blockIdx.x;
    int seg, rel;
    if (bid < 2048){ seg = bid >> 9; rel = bid & 511; }
    else if (bid < 6144){ seg = 4; rel = bid - 2048; }
    else { seg = 5; rel = bid - 6144; }
    int K = (seg==5)? DFF : DM;
    int N = (seg==4)? DFF : DM;
    int nx = N/32, kx = K/32;
    int n0 = (rel % nx)*32;
    int k0 = ((rel / nx) % kx)*32;
    int l  = rel / (nx*kx);
    const float* Wp = a.W[seg] + (size_t)l*K*N;
    bf16* OhP = a.Oh[seg] + (size_t)l*K*N;
    bf16* OlP = a.Ol[seg] + (size_t)l*K*N;
    int tx = threadIdx.x, ty = threadIdx.y;
    #pragma unroll
    for (int i=0;i<4;i++)
        s[ty+8*i][tx] = Wp[(size_t)(k0+ty+8*i)*N + n0+tx];
    __syncthreads();
    #pragma unroll
    for (int i=0;i<4;i++){
        float v = s[tx][ty+8*i];
        bf16 h, lo; split_bf16(v, h, lo);
        size_t o = (size_t)(n0+ty+8*i)*K + k0+tx;
        OhP[o] = h; OlP[o] = lo;
    }
}

// ---------------- embedding (fp32 + bf16 split out) ----------------
__global__ void embed_kernel(const float* __restrict__ px, const float* __restrict__ py,
                             const float* __restrict__ fx,
                             const float* __restrict__ W, const float* __restrict__ b,
                             float* __restrict__ x, bf16* __restrict__ xh, bf16* __restrict__ xl)
{
    __shared__ float s[24];
    int r = blockIdx.x;
    int bb = r / NTOK, n = r % NTOK;
    int t = threadIdx.x;
    if (t < 24) {
        float v;
        if (t < 16) {
            v = (n < SPAST) ? px[(bb*SPAST+n)*16+t] : fx[(bb*SFUT+(n-SPAST))*16+t];
        } else {
            int yn = (n < SPAST) ? n : (SPAST-1);
            v = py[(bb*SPAST+yn)*8 + (t-16)];
        }
        s[t] = v;
    }
    __syncthreads();
    float acc = b[t];
    #pragma unroll
    for (int kk=0; kk<24; kk++) acc = fmaf(s[kk], W[kk*DM+t], acc);
    size_t o = (size_t)r*DM + t;
    x[o] = acc;
    bf16 h, lo; split_bf16(acc, h, lo);
    xh[o] = h; xl[o] = lo;
}

// ---------------- bf16 error-split tensor-core GEMM: register-staged prefetch ----------------
// Block tile 128x64, BK=32. 256 threads = 8 warps in 4(M) x 2(N), each warp 32x32.
// D = Ah*Bh^T + Ah*Bl^T + Al*Bh^T  (fp32 accum)
// EPI: 0 = +bias fp32 out, 1 = elu(x+bias)+1 fp32 out, 2 = relu(x+bias)->bf16 h/l out, 4 = raw fp32 out
#define BM 128
#define BN 64
#define BK 32
#define SAPAD 40   // BK + 8 pad (80B row stride: conflict-free ldmatrix)

template<int EPI>
__device__ void gemm_core(int K, int Ntot, int kbeg, int kend,
    const bf16* __restrict__ Ah, const bf16* __restrict__ Al,
    const bf16* __restrict__ Bh, const bf16* __restrict__ Bl,
    const float* __restrict__ bias,
    float* __restrict__ Cf, bf16* __restrict__ Ch, bf16* __restrict__ Cl)
{
    __shared__ bf16 sAh[BM][SAPAD], sAl[BM][SAPAD];
    __shared__ bf16 sBh[BN][SAPAD], sBl[BN][SAPAD];

    const int t = threadIdx.x;
    const int lane = t & 31, warp = t >> 5;
    const int wm = warp & 3;            // 0..3 : M block of 32
    const int wn = warp >> 2;           // 0..1 : N block of 32
    const int bm = blockIdx.y * BM;
    const int bn = blockIdx.x * BN;

    float acc[2][4][4];
    #pragma unroll
    for (int mt=0;mt<2;mt++)
        #pragma unroll
        for (int nt=0;nt<4;nt++)
            #pragma unroll
            for (int u=0;u<4;u++) acc[mt][nt][u] = 0.f;

    // per-thread load coordinates (same layout as before)
    const int arow = t >> 2;            // 0..63 (second A row = arow+64)
    const int akq  = (t & 3) * 8;       // bf16 element offset within row
    const int brow = t >> 2;            // 0..63
    const int bkq  = (t & 3) * 8;

    const bf16* pAh0 = Ah + (size_t)(bm+arow)*K    + kbeg + akq;
    const bf16* pAh1 = Ah + (size_t)(bm+arow+64)*K + kbeg + akq;
    const bf16* pAl0 = Al + (size_t)(bm+arow)*K    + kbeg + akq;
    const bf16* pAl1 = Al + (size_t)(bm+arow+64)*K + kbeg + akq;
    const bf16* pBh  = Bh + (size_t)(bn+brow)*K    + kbeg + bkq;
    const bf16* pBl  = Bl + (size_t)(bn+brow)*K    + kbeg + bkq;

    // prologue: tile 0 straight to smem
    {
        uint4 a0 = *(const uint4*)pAh0;
        uint4 a1 = *(const uint4*)pAh1;
        uint4 a2 = *(const uint4*)pAl0;
        uint4 a3 = *(const uint4*)pAl1;
        uint4 b0 = *(const uint4*)pBh;
        uint4 b1 = *(const uint4*)pBl;
        *(uint4*)&sAh[arow   ][akq] = a0;
        *(uint4*)&sAh[arow+64][akq] = a1;
        *(uint4*)&sAl[arow   ][akq] = a2;
        *(uint4*)&sAl[arow+64][akq] = a3;
        *(uint4*)&sBh[brow][bkq] = b0;
        *(uint4*)&sBl[brow][bkq] = b1;
    }
    __syncthreads();

    const int nk = (kend - kbeg) / BK;
    for (int kt=0; kt<nk; kt++){
        const bool more = (kt+1 < nk);
        uint4 nAh0, nAh1, nAl0, nAl1, nBh0, nBl0;
        if (more){
            const size_t off = (size_t)(kt+1)*BK;
            nAh0 = *(const uint4*)(pAh0 + off);
            nAh1 = *(const uint4*)(pAh1 + off);
            nAl0 = *(const uint4*)(pAl0 + off);
            nAl1 = *(const uint4*)(pAl1 + off);
            nBh0 = *(const uint4*)(pBh  + off);
            nBl0 = *(const uint4*)(pBl  + off);
        }

        #pragma unroll
        for (int ks=0; ks<2; ks++){
            unsigned ah[2][4], al[2][4], bh[4][2], bl[4][2];
            #pragma unroll
            for (int mt=0;mt<2;mt++){
                int row = wm*32 + mt*16 + (lane & 15);
                int kc  = ks*16 + (lane >> 4)*8;
                ldsm_x4(ah[mt], smem_u32(&sAh[row][kc]));
                ldsm_x4(al[mt], smem_u32(&sAl[row][kc]));
            }
            // merged B loads: one ldsm_x4 covers an nt pair
            #pragma unroll
            for (int ntp=0; ntp<2; ntp++){
                int row = wn*32 + ntp*16 + ((lane >> 4) & 1)*8 + (lane & 7);
                int kc  = ks*16 + ((lane >> 3) & 1)*8;
                unsigned r4[4];
                ldsm_x4(r4, smem_u32(&sBh[row][kc]));
                bh[ntp*2  ][0]=r4[0]; bh[ntp*2  ][1]=r4[1];
                bh[ntp*2+1][0]=r4[2]; bh[ntp*2+1][1]=r4[3];
                ldsm_x4(r4, smem_u32(&sBl[row][kc]));
                bl[ntp*2  ][0]=r4[0]; bl[ntp*2  ][1]=r4[1];
                bl[ntp*2+1][0]=r4[2]; bl[ntp*2+1][1]=r4[3];
            }
            #pragma unroll
            for (int mt=0;mt<2;mt++)
                #pragma unroll
                for (int nt=0;nt<4;nt++){
                    mma16816(acc[mt][nt], ah[mt], bh[nt]);
                    mma16816(acc[mt][nt], ah[mt], bl[nt]);
                    mma16816(acc[mt][nt], al[mt], bh[nt]);
                }
        }
        __syncthreads();
        if (more){
            *(uint4*)&sAh[arow   ][akq] = nAh0;
            *(uint4*)&sAh[arow+64][akq] = nAh1;
            *(uint4*)&sAl[arow   ][akq] = nAl0;
            *(uint4*)&sAl[arow+64][akq] = nAl1;
            *(uint4*)&sBh[brow][bkq] = nBh0;
            *(uint4*)&sBl[brow][bkq] = nBl0;
        }
        __syncthreads();
    }

    // ---- epilogue ----
    #pragma unroll
    for (int mt=0;mt<2;mt++){
        #pragma unroll
        for (int nt=0;nt<4;nt++){
            int col = bn + wn*32 + nt*8 + (lane & 3)*2;
            #pragma unroll
            for (int half=0; half<2; half++){
                int row = bm + wm*32 + mt*16 + (lane >> 2) + half*8;
                float v0 = acc[mt][nt][half*2+0];
                float v1 = acc[mt][nt][half*2+1];
                if (EPI != 4){ v0 += bias[col]; v1 += bias[col+1]; }
                if (EPI == 1){
                    v0 = (v0>=0.f)? v0+1.f : expf(v0);
                    v1 = (v1>=0.f)? v1+1.f : expf(v1);
                }
                if (EPI == 2){
                    v0 = fmaxf(v0, 0.f); v1 = fmaxf(v1, 0.f);
                    bf16 h0,l0,h1,l1; split_bf16(v0,h0,l0); split_bf16(v1,h1,l1);
                    bf162 ph; ph.x=h0; ph.y=h1;
                    bf162 pl; pl.x=l0; pl.y=l1;
                    size_t o = (size_t)row*Ntot + col;
                    *(bf162*)(Ch + o) = ph;
                    *(bf162*)(Cl + o) = pl;
                } else {
                    float2 o2; o2.x=v0; o2.y=v1;
                    *(float2*)(Cf + (size_t)row*Ntot + col) = o2;
                }
            }
        }
    }
}

template<int EPI>
__global__ void __launch_bounds__(256) bgemm_kernel(
    int K, int Ntot, int ksplit,
    const bf16* __restrict__ Ah, const bf16* __restrict__ Al,
    const bf16* __restrict__ Bh, const bf16* __restrict__ Bl,
    const float* __restrict__ bias,
    float* __restrict__ Cf, bf16* __restrict__ Ch, bf16* __restrict__ Cl, size_t cstride)
{
    int z = blockIdx.z;
    gemm_core<EPI>(K, Ntot, z*ksplit, (z+1)*ksplit, Ah, Al, Bh, Bl, bias,
                   Cf + (size_t)z*cstride, Ch, Cl);
}

__global__ void __launch_bounds__(256) qkv_bgemm(
    const bf16* __restrict__ xh, const bf16* __restrict__ xl,
    const bf16* __restrict__ wqh, const bf16* __restrict__ wql, const float* __restrict__ bq,
    const bf16* __restrict__ wkh, const bf16* __restrict__ wkl, const float* __restrict__ bk,
    const bf16* __restrict__ wvh, const bf16* __restrict__ wvl, const float* __restrict__ bv,
    float* __restrict__ q, float* __restrict__ k, float* __restrict__ v)
{
    int z = blockIdx.z;
    if (z == 0)      gemm_core<1>(DM, DM, 0, DM, xh, xl, wqh, wql, bq, q, nullptr, nullptr);
    else if (z == 1) gemm_core<1>(DM, DM, 0, DM, xh, xl, wkh, wkl, bk, k, nullptr, nullptr);
    else             gemm_core<0>(DM, DM, 0, DM, xh, xl, wvh, wvl, bv, v, nullptr, nullptr);
}

// ---------------- per-chunk K^T V state + K column sums ----------------
__global__ void __launch_bounds__(1024) chunk_kv_kernel(const float* __restrict__ k,
                                                        const float* __restrict__ v)
{
    int c = blockIdx.x, bh = blockIdx.y;
    int b = bh >> 3, h = bh & 7;
    __shared__ float ks[CHUNK][DH];
    __shared__ float vs[CHUNK][DH];
    int t = threadIdx.x;
    int base = b*NTOK + c*CHUNK;
    for (int idx=t; idx<CHUNK*DH; idx+=1024){
        int row = idx >> 5, col = idx & 31;
        size_t g = (size_t)(base+row)*DM + h*DH + col;
        ks[row][col] = k[g];
        vs[row][col] = v[g];
    }
    __syncthreads();
    int d = t >> 5, m = t & 31;
    float s = 0.f;
    #pragma unroll 8
    for (int j=0;j<CHUNK;j++) s = fmaf(ks[j][d], vs[j][m], s);
    g_Sloc[((size_t)bh*NCHUNK + c)*DH*DH + d*DH + m] = s;
    if (t < DH){
        float kssum = 0.f;
        #pragma unroll 8
        for (int j=0;j<CHUNK;j++) kssum += ks[j][t];
        g_kloc[((size_t)bh*NCHUNK + c)*DH + t] = kssum;
    }
}

// ---------------- attention output (R6-proven: 128 thr, unroll x2, bf16 h/l out) ----------------
__global__ void __launch_bounds__(128) attn_kernel(const float* __restrict__ q,
                                                   const float* __restrict__ k,
                                                   const float* __restrict__ v,
                                                   bf16* __restrict__ ah_out,
                                                   bf16* __restrict__ al_out)
{
    int c = blockIdx.x, bh = blockIdx.y;
    int b = bh >> 3, h = bh & 7;
    __shared__ float ks[CHUNK][DH];
    __shared__ float vs[CHUNK][DH];
    __shared__ float Ss[DH][DH];
    __shared__ float kss[DH];
    int t = threadIdx.x;
    int base = b*NTOK + c*CHUNK;
    for (int idx=t; idx<CHUNK*DH; idx+=128){
        int row = idx >> 5, col = idx & 31;
        size_t g = (size_t)(base+row)*DM + h*DH + col;
        ks[row][col] = k[g];
        vs[row][col] = v[g];
    }
    for (int idx=t; idx<DH*DH; idx+=128){
        float s = 0.f;
        const float* p = g_Sloc + (size_t)bh*NCHUNK*DH*DH + idx;
        for (int cc=0; cc<c; cc++) s += p[cc*DH*DH];
        Ss[idx>>5][idx&31] = s;
    }
    if (t < DH){
        float s = 0.f;
        const float* p = g_kloc + (size_t)bh*NCHUNK*DH + t;
        for (int cc=0; cc<c; cc++) s += p[cc*DH];
        kss[t] = s;
    }
    __syncthreads();

    float qr[DH], num[DH];
    {
        const float4* qp = (const float4*)(q + (size_t)(base+t)*DM + h*DH);
        #pragma unroll
        for (int d4=0; d4<8; d4++){
            float4 w4 = qp[d4];
            qr[4*d4+0]=w4.x; qr[4*d4+1]=w4.y; qr[4*d4+2]=w4.z; qr[4*d4+3]=w4.w;
        }
    }
    #pragma unroll
    for (int m=0;m<DH;m++) num[m] = 0.f;
    float z = 0.f;

    #pragma unroll
    for (int d=0; d<DH; d++){
        float qa = qr[d];
        z = fmaf(qa, kss[d], z);
        #pragma unroll
        for (int m=0;m<DH;m++) num[m] = fmaf(qa, Ss[d][m], num[m]);
    }
    int jend = t | 31;
    for (int j=0; j<=jend; j+=2){
        float aa0 = 0.f, aa1 = 0.f;
        #pragma unroll
        for (int d=0; d<DH; d++){
            aa0 = fmaf(qr[d], ks[j  ][d], aa0);
            aa1 = fmaf(qr[d], ks[j+1][d], aa1);
        }
        aa0 = (j   <= t) ? aa0 : 0.f;
        aa1 = (j+1 <= t) ? aa1 : 0.f;
        z += aa0 + aa1;
        #pragma unroll
        for (int m=0;m<DH;m++){
            float nm = fmaf(aa0, vs[j][m], num[m]);
            num[m] = fmaf(aa1, vs[j+1][m], nm);
        }
    }
    float inv = 1.f / (z + 1e-6f);
    size_t ob = (size_t)(base+t)*DM + h*DH;
    #pragma unroll
    for (int m=0;m<DH;m+=2){
        float v0 = num[m]*inv, v1 = num[m+1]*inv;
        bf16 h0,l0,h1,l1; split_bf16(v0,h0,l0); split_bf16(v1,h1,l1);
        bf162 ph; ph.x=h0; ph.y=h1;
        bf162 pl; pl.x=l0; pl.y=l1;
        *(bf162*)(ah_out + ob + m) = ph;
        *(bf162*)(al_out + ob + m) = pl;
    }
}

// ---------------- residual + split-K reduce + LayerNorm (fused, + bf16 split out) ----------------
__global__ void __launch_bounds__(256) ln_red_kernel(
    int np, const float* __restrict__ part, size_t pstride,
    const float* __restrict__ xin, const float* __restrict__ bias,
    const float* __restrict__ w, const float* __restrict__ b,
    float* __restrict__ out, bf16* __restrict__ oh, bf16* __restrict__ ol)
{
    __shared__ float red[8], red2[8];
    int r = blockIdx.x, t = threadIdx.x;
    size_t o = (size_t)r*DM + t;
    float v = xin[o] + bias[t];
    for (int i=0;i<np;i++) v += part[(size_t)i*pstride + o];
    float s = v, s2 = v*v;
    #pragma unroll
    for (int off=16;off;off>>=1){ s += __shfl_xor_sync(~0u,s,off); s2 += __shfl_xor_sync(~0u,s2,off); }
    int warp = t >> 5, lane = t & 31;
    if (lane == 0){ red[warp] = s; red2[warp] = s2; }
    __syncthreads();
    float S=0.f, S2=0.f;
    #pragma unroll
    for (int i=0;i<8;i++){ S += red[i]; S2 += red2[i]; }
    float mean = S * (1.f/DM);
    float var  = S2 * (1.f/DM) - mean*mean;
    float ov = (v - mean) * rsqrtf(var + 1e-5f) * w[t] + b[t];
    out[o] = ov;
    bf16 h, lo; split_bf16(ov, h, lo);
    oh[o] = h; ol[o] = lo;
}

// ---------------- head: mean / sigma ----------------
__global__ void __launch_bounds__(256) head_kernel(const float* __restrict__ x,
                                                   const float* __restrict__ mW, const float* __restrict__ mb,
                                                   const float* __restrict__ sW, const float* __restrict__ sb,
                                                   float* __restrict__ out)
{
    __shared__ float sx[DM];
    int r = blockIdx.x;
    int b = r / SFUT, s = r % SFUT;
    const float* xr = x + (size_t)(b*NTOK + SPAST + s)*DM;
    int t = threadIdx.x;
    sx[t] = xr[t];
    __syncthreads();
    int warp = t >> 5, lane = t & 31;
    float am = 0.f, as = 0.f;
    for (int kk=lane; kk<DM; kk+=32){
        float xv = sx[kk];
        am = fmaf(xv, mW[kk*8 + warp], am);
        as = fmaf(xv, sW[kk*8 + warp], as);
    }
    #pragma unroll
    for (int off=16;off;off>>=1){ am += __shfl_xor_sync(~0u,am,off); as += __shfl_xor_sync(~0u,as,off); }
    if (lane == 0){
        int o = r*8 + warp;
        out[o] = am + mb[warp];
        float sp = as + sb[warp];
        float spv = (sp > 20.f) ? sp : log1pf(expf(sp));
        out[BATCH*SFUT*8 + o] = 0.01f + 0.99f*spv;
    }
}

// ---------------- launch ----------------
extern "C" void kernel_launch(void* const* d_in, const int* in_sizes, int n_in,
                              void* d_out, int out_size)
{
    (void)in_sizes; (void)n_in; (void)out_size;
    const float* past_x   = (const float*)d_in[0];
    const float* past_y   = (const float*)d_in[1];
    const float* future_x = (const float*)d_in[2];
    const float* enc_W    = (const float*)d_in[3];
    const float* enc_b    = (const float*)d_in[4];
    const float* Wq  = (const float*)d_in[5];  const float* bq  = (const float*)d_in[6];
    const float* Wk  = (const float*)d_in[7];  const float* bk  = (const float*)d_in[8];
    const float* Wv  = (const float*)d_in[9];  const float* bv  = (const float*)d_in[10];
    const float* Wo  = (const float*)d_in[11]; const float* bo  = (const float*)d_in[12];
    const float* ln1w= (const float*)d_in[13]; const float* ln1b= (const float*)d_in[14];
    const float* W1  = (const float*)d_in[15]; const float* b1  = (const float*)d_in[16];
    const float* W2  = (const float*)d_in[17]; const float* b2  = (const float*)d_in[18];
    const float* ln2w= (const float*)d_in[19]; const float* ln2b= (const float*)d_in[20];
    const float* mW  = (const float*)d_in[21]; const float* mb  = (const float*)d_in[22];
    const float* sW  = (const float*)d_in[23]; const float* sb  = (const float*)d_in[24];

    float *x,*q,*k,*v,*part;
    bf16 *xh,*xl,*ah,*al,*hh,*hl;
    bf16 *wqh,*wql,*wkh,*wkl,*wvh,*wvl,*woh,*wol,*w1h,*w1l,*w2h,*w2l;
    cudaGetSymbolAddress((void**)&x,   g_x);
    cudaGetSymbolAddress((void**)&q,   g_qb);
    cudaGetSymbolAddress((void**)&k,   g_kb);
    cudaGetSymbolAddress((void**)&v,   g_vb);
    cudaGetSymbolAddress((void**)&part,g_part);
    cudaGetSymbolAddress((void**)&xh,  g_xh);  cudaGetSymbolAddress((void**)&xl, g_xl);
    cudaGetSymbolAddress((void**)&ah,  g_ah);  cudaGetSymbolAddress((void**)&al, g_al);
    cudaGetSymbolAddress((void**)&hh,  g_hh);  cudaGetSymbolAddress((void**)&hl, g_hl);
    cudaGetSymbolAddress((void**)&wqh, g_wqh); cudaGetSymbolAddress((void**)&wql, g_wql);
    cudaGetSymbolAddress((void**)&wkh, g_wkh); cudaGetSymbolAddress((void**)&wkl, g_wkl);
    cudaGetSymbolAddress((void**)&wvh, g_wvh); cudaGetSymbolAddress((void**)&wvl, g_wvl);
    cudaGetSymbolAddress((void**)&woh, g_woh); cudaGetSymbolAddress((void**)&wol, g_wol);
    cudaGetSymbolAddress((void**)&w1h, g_w1h); cudaGetSymbolAddress((void**)&w1l, g_w1l);
    cudaGetSymbolAddress((void**)&w2h, g_w2h); cudaGetSymbolAddress((void**)&w2l, g_w2l);

    // fused weight transpose + split (ONE launch; inputs constant -> deterministic)
    {
        ConvArgs ca;
        ca.W[0]=Wq;  ca.Oh[0]=wqh; ca.Ol[0]=wql;
        ca.W[1]=Wk;  ca.Oh[1]=wkh; ca.Ol[1]=wkl;
        ca.W[2]=Wv;  ca.Oh[2]=wvh; ca.Ol[2]=wvl;
        ca.W[3]=Wo;  ca.Oh[3]=woh; ca.Ol[3]=wol;
        ca.W[4]=W1;  ca.Oh[4]=w1h; ca.Ol[4]=w1l;
        ca.W[5]=W2;  ca.Oh[5]=w2h; ca.Ol[5]=w2l;
        convw_all<<<CONV_BLOCKS, dim3(32,8)>>>(ca);
    }

    embed_kernel<<<NROWS, 256>>>(past_x, past_y, future_x, enc_W, enc_b, x, xh, xl);

    dim3 gQKV(DM/BN,  NROWS/BM, 3);    // 4 x 48 x 3
    dim3 gWo (DM/BN,  NROWS/BM, 2);    // split-K 2
    dim3 gFF (DFF/BN, NROWS/BM, 1);    // 32 x 48
    dim3 gW2 (DM/BN,  NROWS/BM, 4);    // split-K 4
    dim3 gA  (NCHUNK, NBH);

    const size_t PS = (size_t)NROWS*DM;

    for (int i=0;i<NLAYERS;i++){
        const size_t wo4 = (size_t)i*DM*DM;
        const size_t wo1 = (size_t)i*DM*DFF;

        qkv_bgemm<<<gQKV, 256>>>(xh, xl,
            wqh+wo4, wql+wo4, bq+i*DM,
            wkh+wo4, wkl+wo4, bk+i*DM,
            wvh+wo4, wvl+wo4, bv+i*DM,
            q, k, v);

        chunk_kv_kernel<<<gA, 1024>>>(k, v);
        attn_kernel<<<gA, 128>>>(q, k, v, ah, al);

        // Wo: split-K=2 raw partials, then fused residual+reduce+LN -> x (+split)
        bgemm_kernel<4><<<gWo, 256>>>(DM, DM, DM/2, ah, al,
            woh+wo4, wol+wo4, nullptr, part, nullptr, nullptr, PS);
        ln_red_kernel<<<NROWS, 256>>>(2, part, PS, x, bo+i*DM, ln1w+i*DM, ln1b+i*DM, x, xh, xl);

        // FFN
        bgemm_kernel<2><<<gFF, 256>>>(DM, DFF, DM, xh, xl,
            w1h+wo1, w1l+wo1, b1+i*DFF, nullptr, hh, hl, 0);
        bgemm_kernel<4><<<gW2, 256>>>(DFF, DM, DFF/4, hh, hl,
            w2h+wo1, w2l+wo1, nullptr, part, nullptr, nullptr, PS);
        ln_red_kernel<<<NROWS, 256>>>(4, part, PS, x, b2+i*DM, ln2w+i*DM, ln2b+i*DM, x, xh, xl);
    }

    head_kernel<<<BATCH*SFUT, 256>>>(x, mW, mb, sW, sb, (float*)d_out);
}

// round 12
// speedup vs baseline: 1.1729x; 1.1729x over previous
#include <cuda_runtime.h>
#include <cuda_bf16.h>
#include <math.h>

#define BATCH 4
#define SPAST 1024
#define SFUT 512
#define NTOK 1536
#define DM 256
#define NH 8
#define DH 32
#define DFF 2048
#define NLAYERS 8
#define NROWS (BATCH*NTOK)        // 6144
#define CHUNK 128
#define NCHUNK (NTOK/CHUNK)       // 12
#define NBH (BATCH*NH)            // 32

typedef unsigned long long ull;
typedef __nv_bfloat16 bf16;
typedef __nv_bfloat162 bf162;

// ---------------- scratch (no allocation allowed) ----------------
__device__ float g_x  [NROWS*DM];
__device__ float g_qb [NROWS*DM];
__device__ float g_kb [NROWS*DM];
__device__ float g_vb [NROWS*DM];
__device__ float g_part[4*NROWS*DM];
__device__ float g_Sloc[NBH*NCHUNK*DH*DH];
__device__ float g_kloc[NBH*NCHUNK*DH];

__device__ bf16 g_xh[NROWS*DM],  g_xl[NROWS*DM];
__device__ bf16 g_ah[NROWS*DM],  g_al[NROWS*DM];
__device__ bf16 g_hh[NROWS*DFF], g_hl[NROWS*DFF];
// transposed K-major weights, hi/lo split: [L][N][K]
__device__ bf16 g_wqh[NLAYERS*DM*DM],  g_wql[NLAYERS*DM*DM];
__device__ bf16 g_wkh[NLAYERS*DM*DM],  g_wkl[NLAYERS*DM*DM];
__device__ bf16 g_wvh[NLAYERS*DM*DM],  g_wvl[NLAYERS*DM*DM];
__device__ bf16 g_woh[NLAYERS*DM*DM],  g_wol[NLAYERS*DM*DM];
__device__ bf16 g_w1h[NLAYERS*DM*DFF], g_w1l[NLAYERS*DM*DFF];
__device__ bf16 g_w2h[NLAYERS*DFF*DM], g_w2l[NLAYERS*DFF*DM];

// ---------------- helpers ----------------
__device__ __forceinline__ void cp_async16(void* dst, const void* src){
    unsigned int sdst = (unsigned int)__cvta_generic_to_shared(dst);
    asm volatile("cp.async.cg.shared.global [%0], [%1], 16;" :: "r"(sdst), "l"(src));
}
__device__ __forceinline__ void cp_commit(){ asm volatile("cp.async.commit_group;"); }
__device__ __forceinline__ void cp_wait0(){ asm volatile("cp.async.wait_group 0;"); }

__device__ __forceinline__ unsigned smem_u32(const void* p){
    return (unsigned)__cvta_generic_to_shared(p);
}
__device__ __forceinline__ void ldsm_x4(unsigned* r, unsigned addr){
    asm volatile("ldmatrix.sync.aligned.m8n8.x4.shared.b16 {%0,%1,%2,%3}, [%4];"
        : "=r"(r[0]), "=r"(r[1]), "=r"(r[2]), "=r"(r[3]) : "r"(addr));
}
__device__ __forceinline__ void mma16816(float* c, const unsigned* a, const unsigned* b){
    asm volatile("mma.sync.aligned.m16n8k16.row.col.f32.bf16.bf16.f32 "
        "{%0,%1,%2,%3}, {%4,%5,%6,%7}, {%8,%9}, {%0,%1,%2,%3};"
        : "+f"(c[0]), "+f"(c[1]), "+f"(c[2]), "+f"(c[3])
        : "r"(a[0]), "r"(a[1]), "r"(a[2]), "r"(a[3]), "r"(b[0]), "r"(b[1]));
}
__device__ __forceinline__ void split_bf16(float v, bf16& h, bf16& l){
    h = __float2bfloat16(v);
    l = __float2bfloat16(v - __bfloat162float(h));
}

// ---------------- fused weight transpose + bf16 split (ONE launch) ----------------
struct ConvArgs {
    const float* W[6];
    bf16* Oh[6];
    bf16* Ol[6];
};
#define CONV_BLOCKS (2048 + 4096 + 4096)

__global__ void convw_all(ConvArgs a)
{
    __shared__ float s[32][33];
    int bid = blockIdx.x;
    int seg, rel;
    if (bid < 2048){ seg = bid >> 9; rel = bid & 511; }
    else if (bid < 6144){ seg = 4; rel = bid - 2048; }
    else { seg = 5; rel = bid - 6144; }
    int K = (seg==5)? DFF : DM;
    int N = (seg==4)? DFF : DM;
    int nx = N/32, kx = K/32;
    int n0 = (rel % nx)*32;
    int k0 = ((rel / nx) % kx)*32;
    int l  = rel / (nx*kx);
    const float* Wp = a.W[seg] + (size_t)l*K*N;
    bf16* OhP = a.Oh[seg] + (size_t)l*K*N;
    bf16* OlP = a.Ol[seg] + (size_t)l*K*N;
    int tx = threadIdx.x, ty = threadIdx.y;
    #pragma unroll
    for (int i=0;i<4;i++)
        s[ty+8*i][tx] = Wp[(size_t)(k0+ty+8*i)*N + n0+tx];
    __syncthreads();
    #pragma unroll
    for (int i=0;i<4;i++){
        float v = s[tx][ty+8*i];
        bf16 h, lo; split_bf16(v, h, lo);
        size_t o = (size_t)(n0+ty+8*i)*K + k0+tx;
        OhP[o] = h; OlP[o] = lo;
    }
}

// ---------------- embedding (fp32 + bf16 split out) ----------------
__global__ void embed_kernel(const float* __restrict__ px, const float* __restrict__ py,
                             const float* __restrict__ fx,
                             const float* __restrict__ W, const float* __restrict__ b,
                             float* __restrict__ x, bf16* __restrict__ xh, bf16* __restrict__ xl)
{
    __shared__ float s[24];
    int r = blockIdx.x;
    int bb = r / NTOK, n = r % NTOK;
    int t = threadIdx.x;
    if (t < 24) {
        float v;
        if (t < 16) {
            v = (n < SPAST) ? px[(bb*SPAST+n)*16+t] : fx[(bb*SFUT+(n-SPAST))*16+t];
        } else {
            int yn = (n < SPAST) ? n : (SPAST-1);
            v = py[(bb*SPAST+yn)*8 + (t-16)];
        }
        s[t] = v;
    }
    __syncthreads();
    float acc = b[t];
    #pragma unroll
    for (int kk=0; kk<24; kk++) acc = fmaf(s[kk], W[kk*DM+t], acc);
    size_t o = (size_t)r*DM + t;
    x[o] = acc;
    bf16 h, lo; split_bf16(acc, h, lo);
    xh[o] = h; xl[o] = lo;
}

// ---------------- bf16 error-split tensor-core GEMM (mma.sync, cp.async, BK=64) ----------------
// Block tile 128x64, BK=64. 256 threads = 8 warps in 4(M) x 2(N), each warp 32x32.
// D = Ah*Bh^T + Ah*Bl^T + Al*Bh^T  (fp32 accum)
// EPI: 0 = +bias fp32 out, 1 = elu(x+bias)+1 fp32 out, 2 = relu(x+bias)->bf16 h/l out, 4 = raw fp32 out
#define BM 128
#define BN 64
#define BK 64
#define SAPAD 72   // BK + 8 pad (144B row stride; ldmatrix 8-row phases conflict-free)
// dynamic smem: Ah/Al [128][72] + Bh/Bl [64][72], bf16
#define GSM_AH 0
#define GSM_AL (BM*SAPAD)
#define GSM_BH (2*BM*SAPAD)
#define GSM_BL (2*BM*SAPAD + BN*SAPAD)
#define GSMEM ((2*BM*SAPAD + 2*BN*SAPAD)*2)   // 55296 bytes

template<int EPI>
__device__ void gemm_core(int K, int Ntot, int kbeg, int kend,
    const bf16* __restrict__ Ah, const bf16* __restrict__ Al,
    const bf16* __restrict__ Bh, const bf16* __restrict__ Bl,
    const float* __restrict__ bias,
    float* __restrict__ Cf, bf16* __restrict__ Ch, bf16* __restrict__ Cl)
{
    extern __shared__ bf16 gsm[];
    bf16* sAh = gsm + GSM_AH;
    bf16* sAl = gsm + GSM_AL;
    bf16* sBh = gsm + GSM_BH;
    bf16* sBl = gsm + GSM_BL;

    const int t = threadIdx.x;
    const int lane = t & 31, warp = t >> 5;
    const int wm = warp & 3;            // 0..3 : M block of 32
    const int wn = warp >> 2;           // 0..1 : N block of 32
    const int bm = blockIdx.y * BM;
    const int bn = blockIdx.x * BN;

    float acc[2][4][4];
    #pragma unroll
    for (int mt=0;mt<2;mt++)
        #pragma unroll
        for (int nt=0;nt<4;nt++)
            #pragma unroll
            for (int u=0;u<4;u++) acc[mt][nt][u] = 0.f;

    for (int k0=kbeg; k0<kend; k0+=BK){
        // A: 128 rows x 64 bf16 = 1024 uint4 per matrix; 4 per thread each (h, l)
        #pragma unroll
        for (int i=0;i<4;i++){
            int idx = t + i*256;
            int row = idx >> 3, kp = (idx & 7)*8;     // 8 bf16 per 16B chunk
            size_t go = (size_t)(bm+row)*K + k0 + kp;
            cp_async16(sAh + row*SAPAD + kp, Ah + go);
            cp_async16(sAl + row*SAPAD + kp, Al + go);
        }
        // B: 64 rows x 64 bf16 = 512 uint4 per matrix; 2 per thread each
        #pragma unroll
        for (int i=0;i<2;i++){
            int idx = t + i*256;
            int row = idx >> 3, kp = (idx & 7)*8;
            size_t go = (size_t)(bn+row)*K + k0 + kp;
            cp_async16(sBh + row*SAPAD + kp, Bh + go);
            cp_async16(sBl + row*SAPAD + kp, Bl + go);
        }
        cp_commit(); cp_wait0();
        __syncthreads();

        #pragma unroll
        for (int ks=0; ks<4; ks++){
            unsigned ah[2][4], al[2][4], bh[4][2], bl[4][2];
            #pragma unroll
            for (int mt=0;mt<2;mt++){
                int row = wm*32 + mt*16 + (lane & 15);
                int kc  = ks*16 + (lane >> 4)*8;
                ldsm_x4(ah[mt], smem_u32(sAh + row*SAPAD + kc));
                ldsm_x4(al[mt], smem_u32(sAl + row*SAPAD + kc));
            }
            // merged B loads: one ldsm_x4 covers an nt pair
            #pragma unroll
            for (int ntp=0; ntp<2; ntp++){
                int row = wn*32 + ntp*16 + ((lane >> 4) & 1)*8 + (lane & 7);
                int kc  = ks*16 + ((lane >> 3) & 1)*8;
                unsigned r4[4];
                ldsm_x4(r4, smem_u32(sBh + row*SAPAD + kc));
                bh[ntp*2  ][0]=r4[0]; bh[ntp*2  ][1]=r4[1];
                bh[ntp*2+1][0]=r4[2]; bh[ntp*2+1][1]=r4[3];
                ldsm_x4(r4, smem_u32(sBl + row*SAPAD + kc));
                bl[ntp*2  ][0]=r4[0]; bl[ntp*2  ][1]=r4[1];
                bl[ntp*2+1][0]=r4[2]; bl[ntp*2+1][1]=r4[3];
            }
            #pragma unroll
            for (int mt=0;mt<2;mt++)
                #pragma unroll
                for (int nt=0;nt<4;nt++){
                    mma16816(acc[mt][nt], ah[mt], bh[nt]);
                    mma16816(acc[mt][nt], ah[mt], bl[nt]);
                    mma16816(acc[mt][nt], al[mt], bh[nt]);
                }
        }
        __syncthreads();
    }

    // ---- epilogue ----
    #pragma unroll
    for (int mt=0;mt<2;mt++){
        #pragma unroll
        for (int nt=0;nt<4;nt++){
            int col = bn + wn*32 + nt*8 + (lane & 3)*2;
            #pragma unroll
            for (int half=0; half<2; half++){
                int row = bm + wm*32 + mt*16 + (lane >> 2) + half*8;
                float v0 = acc[mt][nt][half*2+0];
                float v1 = acc[mt][nt][half*2+1];
                if (EPI != 4){ v0 += bias[col]; v1 += bias[col+1]; }
                if (EPI == 1){
                    v0 = (v0>=0.f)? v0+1.f : expf(v0);
                    v1 = (v1>=0.f)? v1+1.f : expf(v1);
                }
                if (EPI == 2){
                    v0 = fmaxf(v0, 0.f); v1 = fmaxf(v1, 0.f);
                    bf16 h0,l0,h1,l1; split_bf16(v0,h0,l0); split_bf16(v1,h1,l1);
                    bf162 ph; ph.x=h0; ph.y=h1;
                    bf162 pl; pl.x=l0; pl.y=l1;
                    size_t o = (size_t)row*Ntot + col;
                    *(bf162*)(Ch + o) = ph;
                    *(bf162*)(Cl + o) = pl;
                } else {
                    float2 o2; o2.x=v0; o2.y=v1;
                    *(float2*)(Cf + (size_t)row*Ntot + col) = o2;
                }
            }
        }
    }
}

template<int EPI>
__global__ void __launch_bounds__(256) bgemm_kernel(
    int K, int Ntot, int ksplit,
    const bf16* __restrict__ Ah, const bf16* __restrict__ Al,
    const bf16* __restrict__ Bh, const bf16* __restrict__ Bl,
    const float* __restrict__ bias,
    float* __restrict__ Cf, bf16* __restrict__ Ch, bf16* __restrict__ Cl, size_t cstride)
{
    int z = blockIdx.z;
    gemm_core<EPI>(K, Ntot, z*ksplit, (z+1)*ksplit, Ah, Al, Bh, Bl, bias,
                   Cf + (size_t)z*cstride, Ch, Cl);
}

__global__ void __launch_bounds__(256) qkv_bgemm(
    const bf16* __restrict__ xh, const bf16* __restrict__ xl,
    const bf16* __restrict__ wqh, const bf16* __restrict__ wql, const float* __restrict__ bq,
    const bf16* __restrict__ wkh, const bf16* __restrict__ wkl, const float* __restrict__ bk,
    const bf16* __restrict__ wvh, const bf16* __restrict__ wvl, const float* __restrict__ bv,
    float* __restrict__ q, float* __restrict__ k, float* __restrict__ v)
{
    int z = blockIdx.z;
    if (z == 0)      gemm_core<1>(DM, DM, 0, DM, xh, xl, wqh, wql, bq, q, nullptr, nullptr);
    else if (z == 1) gemm_core<1>(DM, DM, 0, DM, xh, xl, wkh, wkl, bk, k, nullptr, nullptr);
    else             gemm_core<0>(DM, DM, 0, DM, xh, xl, wvh, wvl, bv, v, nullptr, nullptr);
}

// ---------------- per-chunk K^T V state + K column sums (vectorized: 256 thr, 4 out/thr) ----------------
__global__ void __launch_bounds__(256) chunk_kv_kernel(const float* __restrict__ k,
                                                       const float* __restrict__ v)
{
    int c = blockIdx.x, bh = blockIdx.y;
    int b = bh >> 3, h = bh & 7;
    __shared__ float ks[CHUNK][DH];
    __shared__ float vs[CHUNK][DH];
    int t = threadIdx.x;
    int base = b*NTOK + c*CHUNK;
    for (int idx=t; idx<CHUNK*8; idx+=256){
        int row = idx >> 3, c4 = (idx & 7)*4;
        size_t g = (size_t)(base+row)*DM + h*DH + c4;
        *(float4*)&ks[row][c4] = *(const float4*)(k + g);
        *(float4*)&vs[row][c4] = *(const float4*)(v + g);
    }
    __syncthreads();
    int d = t >> 3, m0 = (t & 7)*4;
    float s0=0.f, s1=0.f, s2=0.f, s3=0.f;
    #pragma unroll 4
    for (int j=0;j<CHUNK;j++){
        float kv = ks[j][d];
        float4 vv = *(const float4*)&vs[j][m0];
        s0 = fmaf(kv, vv.x, s0);
        s1 = fmaf(kv, vv.y, s1);
        s2 = fmaf(kv, vv.z, s2);
        s3 = fmaf(kv, vv.w, s3);
    }
    float4 o4; o4.x=s0; o4.y=s1; o4.z=s2; o4.w=s3;
    *(float4*)(g_Sloc + ((size_t)bh*NCHUNK + c)*DH*DH + d*DH + m0) = o4;
    if (t < DH){
        float kssum = 0.f;
        #pragma unroll 8
        for (int j=0;j<CHUNK;j++) kssum += ks[j][t];
        g_kloc[((size_t)bh*NCHUNK + c)*DH + t] = kssum;
    }
}

// ---------------- attention output (R6-proven: 128 thr, unroll x2, bf16 h/l out) ----------------
__global__ void __launch_bounds__(128) attn_kernel(const float* __restrict__ q,
                                                   const float* __restrict__ k,
                                                   const float* __restrict__ v,
                                                   bf16* __restrict__ ah_out,
                                                   bf16* __restrict__ al_out)
{
    int c = blockIdx.x, bh = blockIdx.y;
    int b = bh >> 3, h = bh & 7;
    __shared__ float ks[CHUNK][DH];
    __shared__ float vs[CHUNK][DH];
    __shared__ float Ss[DH][DH];
    __shared__ float kss[DH];
    int t = threadIdx.x;
    int base = b*NTOK + c*CHUNK;
    for (int idx=t; idx<CHUNK*DH; idx+=128){
        int row = idx >> 5, col = idx & 31;
        size_t g = (size_t)(base+row)*DM + h*DH + col;
        ks[row][col] = k[g];
        vs[row][col] = v[g];
    }
    for (int idx=t; idx<DH*DH; idx+=128){
        float s = 0.f;
        const float* p = g_Sloc + (size_t)bh*NCHUNK*DH*DH + idx;
        for (int cc=0; cc<c; cc++) s += p[cc*DH*DH];
        Ss[idx>>5][idx&31] = s;
    }
    if (t < DH){
        float s = 0.f;
        const float* p = g_kloc + (size_t)bh*NCHUNK*DH + t;
        for (int cc=0; cc<c; cc++) s += p[cc*DH];
        kss[t] = s;
    }
    __syncthreads();

    float qr[DH], num[DH];
    {
        const float4* qp = (const float4*)(q + (size_t)(base+t)*DM + h*DH);
        #pragma unroll
        for (int d4=0; d4<8; d4++){
            float4 w4 = qp[d4];
            qr[4*d4+0]=w4.x; qr[4*d4+1]=w4.y; qr[4*d4+2]=w4.z; qr[4*d4+3]=w4.w;
        }
    }
    #pragma unroll
    for (int m=0;m<DH;m++) num[m] = 0.f;
    float z = 0.f;

    #pragma unroll
    for (int d=0; d<DH; d++){
        float qa = qr[d];
        z = fmaf(qa, kss[d], z);
        #pragma unroll
        for (int m=0;m<DH;m++) num[m] = fmaf(qa, Ss[d][m], num[m]);
    }
    int jend = t | 31;
    for (int j=0; j<=jend; j+=2){
        float aa0 = 0.f, aa1 = 0.f;
        #pragma unroll
        for (int d=0; d<DH; d++){
            aa0 = fmaf(qr[d], ks[j  ][d], aa0);
            aa1 = fmaf(qr[d], ks[j+1][d], aa1);
        }
        aa0 = (j   <= t) ? aa0 : 0.f;
        aa1 = (j+1 <= t) ? aa1 : 0.f;
        z += aa0 + aa1;
        #pragma unroll
        for (int m=0;m<DH;m++){
            float nm = fmaf(aa0, vs[j][m], num[m]);
            num[m] = fmaf(aa1, vs[j+1][m], nm);
        }
    }
    float inv = 1.f / (z + 1e-6f);
    size_t ob = (size_t)(base+t)*DM + h*DH;
    #pragma unroll
    for (int m=0;m<DH;m+=2){
        float v0 = num[m]*inv, v1 = num[m+1]*inv;
        bf16 h0,l0,h1,l1; split_bf16(v0,h0,l0); split_bf16(v1,h1,l1);
        bf162 ph; ph.x=h0; ph.y=h1;
        bf162 pl; pl.x=l0; pl.y=l1;
        *(bf162*)(ah_out + ob + m) = ph;
        *(bf162*)(al_out + ob + m) = pl;
    }
}

// ---------------- residual + split-K reduce + LayerNorm (fused, + bf16 split out) ----------------
__global__ void __launch_bounds__(256) ln_red_kernel(
    int np, const float* __restrict__ part, size_t pstride,
    const float* __restrict__ xin, const float* __restrict__ bias,
    const float* __restrict__ w, const float* __restrict__ b,
    float* __restrict__ out, bf16* __restrict__ oh, bf16* __restrict__ ol)
{
    __shared__ float red[8], red2[8];
    int r = blockIdx.x, t = threadIdx.x;
    size_t o = (size_t)r*DM + t;
    float v = xin[o] + bias[t];
    for (int i=0;i<np;i++) v += part[(size_t)i*pstride + o];
    float s = v, s2 = v*v;
    #pragma unroll
    for (int off=16;off;off>>=1){ s += __shfl_xor_sync(~0u,s,off); s2 += __shfl_xor_sync(~0u,s2,off); }
    int warp = t >> 5, lane = t & 31;
    if (lane == 0){ red[warp] = s; red2[warp] = s2; }
    __syncthreads();
    float S=0.f, S2=0.f;
    #pragma unroll
    for (int i=0;i<8;i++){ S += red[i]; S2 += red2[i]; }
    float mean = S * (1.f/DM);
    float var  = S2 * (1.f/DM) - mean*mean;
    float ov = (v - mean) * rsqrtf(var + 1e-5f) * w[t] + b[t];
    out[o] = ov;
    bf16 h, lo; split_bf16(ov, h, lo);
    oh[o] = h; ol[o] = lo;
}

// ---------------- head: mean / sigma ----------------
__global__ void __launch_bounds__(256) head_kernel(const float* __restrict__ x,
                                                   const float* __restrict__ mW, const float* __restrict__ mb,
                                                   const float* __restrict__ sW, const float* __restrict__ sb,
                                                   float* __restrict__ out)
{
    __shared__ float sx[DM];
    int r = blockIdx.x;
    int b = r / SFUT, s = r % SFUT;
    const float* xr = x + (size_t)(b*NTOK + SPAST + s)*DM;
    int t = threadIdx.x;
    sx[t] = xr[t];
    __syncthreads();
    int warp = t >> 5, lane = t & 31;
    float am = 0.f, as = 0.f;
    for (int kk=lane; kk<DM; kk+=32){
        float xv = sx[kk];
        am = fmaf(xv, mW[kk*8 + warp], am);
        as = fmaf(xv, sW[kk*8 + warp], as);
    }
    #pragma unroll
    for (int off=16;off;off>>=1){ am += __shfl_xor_sync(~0u,am,off); as += __shfl_xor_sync(~0u,as,off); }
    if (lane == 0){
        int o = r*8 + warp;
        out[o] = am + mb[warp];
        float sp = as + sb[warp];
        float spv = (sp > 20.f) ? sp : log1pf(expf(sp));
        out[BATCH*SFUT*8 + o] = 0.01f + 0.99f*spv;
    }
}

// ---------------- launch ----------------
extern "C" void kernel_launch(void* const* d_in, const int* in_sizes, int n_in,
                              void* d_out, int out_size)
{
    (void)in_sizes; (void)n_in; (void)out_size;
    const float* past_x   = (const float*)d_in[0];
    const float* past_y   = (const float*)d_in[1];
    const float* future_x = (const float*)d_in[2];
    const float* enc_W    = (const float*)d_in[3];
    const float* enc_b    = (const float*)d_in[4];
    const float* Wq  = (const float*)d_in[5];  const float* bq  = (const float*)d_in[6];
    const float* Wk  = (const float*)d_in[7];  const float* bk  = (const float*)d_in[8];
    const float* Wv  = (const float*)d_in[9];  const float* bv  = (const float*)d_in[10];
    const float* Wo  = (const float*)d_in[11]; const float* bo  = (const float*)d_in[12];
    const float* ln1w= (const float*)d_in[13]; const float* ln1b= (const float*)d_in[14];
    const float* W1  = (const float*)d_in[15]; const float* b1  = (const float*)d_in[16];
    const float* W2  = (const float*)d_in[17]; const float* b2  = (const float*)d_in[18];
    const float* ln2w= (const float*)d_in[19]; const float* ln2b= (const float*)d_in[20];
    const float* mW  = (const float*)d_in[21]; const float* mb  = (const float*)d_in[22];
    const float* sW  = (const float*)d_in[23]; const float* sb  = (const float*)d_in[24];

    float *x,*q,*k,*v,*part;
    bf16 *xh,*xl,*ah,*al,*hh,*hl;
    bf16 *wqh,*wql,*wkh,*wkl,*wvh,*wvl,*woh,*wol,*w1h,*w1l,*w2h,*w2l;
    cudaGetSymbolAddress((void**)&x,   g_x);
    cudaGetSymbolAddress((void**)&q,   g_qb);
    cudaGetSymbolAddress((void**)&k,   g_kb);
    cudaGetSymbolAddress((void**)&v,   g_vb);
    cudaGetSymbolAddress((void**)&part,g_part);
    cudaGetSymbolAddress((void**)&xh,  g_xh);  cudaGetSymbolAddress((void**)&xl, g_xl);
    cudaGetSymbolAddress((void**)&ah,  g_ah);  cudaGetSymbolAddress((void**)&al, g_al);
    cudaGetSymbolAddress((void**)&hh,  g_hh);  cudaGetSymbolAddress((void**)&hl, g_hl);
    cudaGetSymbolAddress((void**)&wqh, g_wqh); cudaGetSymbolAddress((void**)&wql, g_wql);
    cudaGetSymbolAddress((void**)&wkh, g_wkh); cudaGetSymbolAddress((void**)&wkl, g_wkl);
    cudaGetSymbolAddress((void**)&wvh, g_wvh); cudaGetSymbolAddress((void**)&wvl, g_wvl);
    cudaGetSymbolAddress((void**)&woh, g_woh); cudaGetSymbolAddress((void**)&wol, g_wol);
    cudaGetSymbolAddress((void**)&w1h, g_w1h); cudaGetSymbolAddress((void**)&w1l, g_w1l);
    cudaGetSymbolAddress((void**)&w2h, g_w2h); cudaGetSymbolAddress((void**)&w2l, g_w2l);

    cudaFuncSetAttribute(qkv_bgemm,       cudaFuncAttributeMaxDynamicSharedMemorySize, GSMEM);
    cudaFuncSetAttribute(bgemm_kernel<2>, cudaFuncAttributeMaxDynamicSharedMemorySize, GSMEM);
    cudaFuncSetAttribute(bgemm_kernel<4>, cudaFuncAttributeMaxDynamicSharedMemorySize, GSMEM);

    // fused weight transpose + split (ONE launch; inputs constant -> deterministic)
    {
        ConvArgs ca;
        ca.W[0]=Wq;  ca.Oh[0]=wqh; ca.Ol[0]=wql;
        ca.W[1]=Wk;  ca.Oh[1]=wkh; ca.Ol[1]=wkl;
        ca.W[2]=Wv;  ca.Oh[2]=wvh; ca.Ol[2]=wvl;
        ca.W[3]=Wo;  ca.Oh[3]=woh; ca.Ol[3]=wol;
        ca.W[4]=W1;  ca.Oh[4]=w1h; ca.Ol[4]=w1l;
        ca.W[5]=W2;  ca.Oh[5]=w2h; ca.Ol[5]=w2l;
        convw_all<<<CONV_BLOCKS, dim3(32,8)>>>(ca);
    }

    embed_kernel<<<NROWS, 256>>>(past_x, past_y, future_x, enc_W, enc_b, x, xh, xl);

    dim3 gQKV(DM/BN,  NROWS/BM, 3);    // 4 x 48 x 3
    dim3 gWo (DM/BN,  NROWS/BM, 2);    // split-K 2
    dim3 gFF (DFF/BN, NROWS/BM, 1);    // 32 x 48
    dim3 gW2 (DM/BN,  NROWS/BM, 4);    // split-K 4
    dim3 gA  (NCHUNK, NBH);

    const size_t PS = (size_t)NROWS*DM;

    for (int i=0;i<NLAYERS;i++){
        const size_t wo4 = (size_t)i*DM*DM;
        const size_t wo1 = (size_t)i*DM*DFF;

        qkv_bgemm<<<gQKV, 256, GSMEM>>>(xh, xl,
            wqh+wo4, wql+wo4, bq+i*DM,
            wkh+wo4, wkl+wo4, bk+i*DM,
            wvh+wo4, wvl+wo4, bv+i*DM,
            q, k, v);

        chunk_kv_kernel<<<gA, 256>>>(k, v);
        attn_kernel<<<gA, 128>>>(q, k, v, ah, al);

        // Wo: split-K=2 raw partials, then fused residual+reduce+LN -> x (+split)
        bgemm_kernel<4><<<gWo, 256, GSMEM>>>(DM, DM, DM/2, ah, al,
            woh+wo4, wol+wo4, nullptr, part, nullptr, nullptr, PS);
        ln_red_kernel<<<NROWS, 256>>>(2, part, PS, x, bo+i*DM, ln1w+i*DM, ln1b+i*DM, x, xh, xl);

        // FFN
        bgemm_kernel<2><<<gFF, 256, GSMEM>>>(DM, DFF, DM, xh, xl,
            w1h+wo1, w1l+wo1, b1+i*DFF, nullptr, hh, hl, 0);
        bgemm_kernel<4><<<gW2, 256, GSMEM>>>(DFF, DM, DFF/4, hh, hl,
            w2h+wo1, w2l+wo1, nullptr, part, nullptr, nullptr, PS);
        ln_red_kernel<<<NROWS, 256>>>(4, part, PS, x, b2+i*DM, ln2w+i*DM, ln2b+i*DM, x, xh, xl);
    }

    head_kernel<<<BATCH*SFUT, 256>>>(x, mW, mb, sW, sb, (float*)d_out);
}

// round 14
// speedup vs baseline: 1.2289x; 1.0477x over previous
#include <cuda_runtime.h>
#include <cuda_bf16.h>
#include <math.h>

#define BATCH 4
#define SPAST 1024
#define SFUT 512
#define NTOK 1536
#define DM 256
#define NH 8
#define DH 32
#define DFF 2048
#define NLAYERS 8
#define NROWS (BATCH*NTOK)        // 6144
#define CHUNK 64
#define NCHUNK (NTOK/CHUNK)       // 24
#define NBH (BATCH*NH)            // 32

typedef unsigned long long ull;
typedef __nv_bfloat16 bf16;
typedef __nv_bfloat162 bf162;

// ---------------- scratch (no allocation allowed) ----------------
__device__ float g_x  [NROWS*DM];
__device__ float g_qb [NROWS*DM];
__device__ float g_kb [NROWS*DM];
__device__ float g_vb [NROWS*DM];
__device__ float g_part[4*NROWS*DM];
__device__ float g_Sloc[NBH*NCHUNK*DH*DH];
__device__ float g_kloc[NBH*NCHUNK*DH];

__device__ bf16 g_xh[NROWS*DM],  g_xl[NROWS*DM];
__device__ bf16 g_ah[NROWS*DM],  g_al[NROWS*DM];
__device__ bf16 g_hh[NROWS*DFF], g_hl[NROWS*DFF];
// transposed K-major weights, hi/lo split: [L][N][K]
__device__ bf16 g_wqh[NLAYERS*DM*DM],  g_wql[NLAYERS*DM*DM];
__device__ bf16 g_wkh[NLAYERS*DM*DM],  g_wkl[NLAYERS*DM*DM];
__device__ bf16 g_wvh[NLAYERS*DM*DM],  g_wvl[NLAYERS*DM*DM];
__device__ bf16 g_woh[NLAYERS*DM*DM],  g_wol[NLAYERS*DM*DM];
__device__ bf16 g_w1h[NLAYERS*DM*DFF], g_w1l[NLAYERS*DM*DFF];
__device__ bf16 g_w2h[NLAYERS*DFF*DM], g_w2l[NLAYERS*DFF*DM];

// ---------------- helpers ----------------
__device__ __forceinline__ void cp_async16(void* dst, const void* src){
    unsigned int sdst = (unsigned int)__cvta_generic_to_shared(dst);
    asm volatile("cp.async.cg.shared.global [%0], [%1], 16;" :: "r"(sdst), "l"(src));
}
__device__ __forceinline__ void cp_commit(){ asm volatile("cp.async.commit_group;"); }
__device__ __forceinline__ void cp_wait0(){ asm volatile("cp.async.wait_group 0;"); }

__device__ __forceinline__ unsigned smem_u32(const void* p){
    return (unsigned)__cvta_generic_to_shared(p);
}
__device__ __forceinline__ void ldsm_x4(unsigned* r, unsigned addr){
    asm volatile("ldmatrix.sync.aligned.m8n8.x4.shared.b16 {%0,%1,%2,%3}, [%4];"
        : "=r"(r[0]), "=r"(r[1]), "=r"(r[2]), "=r"(r[3]) : "r"(addr));
}
__device__ __forceinline__ void mma16816(float* c, const unsigned* a, const unsigned* b){
    asm volatile("mma.sync.aligned.m16n8k16.row.col.f32.bf16.bf16.f32 "
        "{%0,%1,%2,%3}, {%4,%5,%6,%7}, {%8,%9}, {%0,%1,%2,%3};"
        : "+f"(c[0]), "+f"(c[1]), "+f"(c[2]), "+f"(c[3])
        : "r"(a[0]), "r"(a[1]), "r"(a[2]), "r"(a[3]), "r"(b[0]), "r"(b[1]));
}
__device__ __forceinline__ void split_bf16(float v, bf16& h, bf16& l){
    h = __float2bfloat16(v);
    l = __float2bfloat16(v - __bfloat162float(h));
}

// ---------------- fused weight transpose + bf16 split (ONE launch) ----------------
struct ConvArgs {
    const float* W[6];
    bf16* Oh[6];
    bf16* Ol[6];
};
#define CONV_BLOCKS (2048 + 4096 + 4096)

__global__ void convw_all(ConvArgs a)
{
    __shared__ float s[32][33];
    int bid = blockIdx.x;
    int seg, rel;
    if (bid < 2048){ seg = bid >> 9; rel = bid & 511; }
    else if (bid < 6144){ seg = 4; rel = bid - 2048; }
    else { seg = 5; rel = bid - 6144; }
    int K = (seg==5)? DFF : DM;
    int N = (seg==4)? DFF : DM;
    int nx = N/32, kx = K/32;
    int n0 = (rel % nx)*32;
    int k0 = ((rel / nx) % kx)*32;
    int l  = rel / (nx*kx);
    const float* Wp = a.W[seg] + (size_t)l*K*N;
    bf16* OhP = a.Oh[seg] + (size_t)l*K*N;
    bf16* OlP = a.Ol[seg] + (size_t)l*K*N;
    int tx = threadIdx.x, ty = threadIdx.y;
    #pragma unroll
    for (int i=0;i<4;i++)
        s[ty+8*i][tx] = Wp[(size_t)(k0+ty+8*i)*N + n0+tx];
    __syncthreads();
    #pragma unroll
    for (int i=0;i<4;i++){
        float v = s[tx][ty+8*i];
        bf16 h, lo; split_bf16(v, h, lo);
        size_t o = (size_t)(n0+ty+8*i)*K + k0+tx;
        OhP[o] = h; OlP[o] = lo;
    }
}

// ---------------- embedding (fp32 + bf16 split out) ----------------
__global__ void embed_kernel(const float* __restrict__ px, const float* __restrict__ py,
                             const float* __restrict__ fx,
                             const float* __restrict__ W, const float* __restrict__ b,
                             float* __restrict__ x, bf16* __restrict__ xh, bf16* __restrict__ xl)
{
    __shared__ float s[24];
    int r = blockIdx.x;
    int bb = r / NTOK, n = r % NTOK;
    int t = threadIdx.x;
    if (t < 24) {
        float v;
        if (t < 16) {
            v = (n < SPAST) ? px[(bb*SPAST+n)*16+t] : fx[(bb*SFUT+(n-SPAST))*16+t];
        } else {
            int yn = (n < SPAST) ? n : (SPAST-1);
            v = py[(bb*SPAST+yn)*8 + (t-16)];
        }
        s[t] = v;
    }
    __syncthreads();
    float acc = b[t];
    #pragma unroll
    for (int kk=0; kk<24; kk++) acc = fmaf(s[kk], W[kk*DM+t], acc);
    size_t o = (size_t)r*DM + t;
    x[o] = acc;
    bf16 h, lo; split_bf16(acc, h, lo);
    xh[o] = h; xl[o] = lo;
}

// ---------------- bf16 error-split tensor-core GEMM (mma.sync, cp.async, BK=64) ----------------
// Block tile 128x64, BK=64. 256 threads = 8 warps in 4(M) x 2(N), each warp 32x32.
// D = Ah*Bh^T + Ah*Bl^T + Al*Bh^T  (fp32 accum)
// EPI: 0 = +bias fp32 out, 1 = elu(x+bias)+1 fp32 out, 2 = relu(x+bias)->bf16 h/l out, 4 = raw fp32 out
#define BM 128
#define BN 64
#define BK 64
#define SAPAD 72   // BK + 8 pad (144B row stride; ldmatrix 8-row phases conflict-free)
#define GSM_AH 0
#define GSM_AL (BM*SAPAD)
#define GSM_BH (2*BM*SAPAD)
#define GSM_BL (2*BM*SAPAD + BN*SAPAD)
#define GSMEM ((2*BM*SAPAD + 2*BN*SAPAD)*2)   // 55296 bytes

template<int EPI>
__device__ void gemm_core(int K, int Ntot, int kbeg, int kend,
    const bf16* __restrict__ Ah, const bf16* __restrict__ Al,
    const bf16* __restrict__ Bh, const bf16* __restrict__ Bl,
    const float* __restrict__ bias,
    float* __restrict__ Cf, bf16* __restrict__ Ch, bf16* __restrict__ Cl)
{
    extern __shared__ bf16 gsm[];
    bf16* sAh = gsm + GSM_AH;
    bf16* sAl = gsm + GSM_AL;
    bf16* sBh = gsm + GSM_BH;
    bf16* sBl = gsm + GSM_BL;

    const int t = threadIdx.x;
    const int lane = t & 31, warp = t >> 5;
    const int wm = warp & 3;            // 0..3 : M block of 32
    const int wn = warp >> 2;           // 0..1 : N block of 32
    const int bm = blockIdx.y * BM;
    const int bn = blockIdx.x * BN;

    float acc[2][4][4];
    #pragma unroll
    for (int mt=0;mt<2;mt++)
        #pragma unroll
        for (int nt=0;nt<4;nt++)
            #pragma unroll
            for (int u=0;u<4;u++) acc[mt][nt][u] = 0.f;

    for (int k0=kbeg; k0<kend; k0+=BK){
        // A: 128 rows x 64 bf16 = 1024 uint4 per matrix; 4 per thread each (h, l)
        #pragma unroll
        for (int i=0;i<4;i++){
            int idx = t + i*256;
            int row = idx >> 3, kp = (idx & 7)*8;     // 8 bf16 per 16B chunk
            size_t go = (size_t)(bm+row)*K + k0 + kp;
            cp_async16(sAh + row*SAPAD + kp, Ah + go);
            cp_async16(sAl + row*SAPAD + kp, Al + go);
        }
        // B: 64 rows x 64 bf16 = 512 uint4 per matrix; 2 per thread each
        #pragma unroll
        for (int i=0;i<2;i++){
            int idx = t + i*256;
            int row = idx >> 3, kp = (idx & 7)*8;
            size_t go = (size_t)(bn+row)*K + k0 + kp;
            cp_async16(sBh + row*SAPAD + kp, Bh + go);
            cp_async16(sBl + row*SAPAD + kp, Bl + go);
        }
        cp_commit(); cp_wait0();
        __syncthreads();

        #pragma unroll
        for (int ks=0; ks<4; ks++){
            unsigned ah[2][4], al[2][4], bh[4][2], bl[4][2];
            #pragma unroll
            for (int mt=0;mt<2;mt++){
                int row = wm*32 + mt*16 + (lane & 15);
                int kc  = ks*16 + (lane >> 4)*8;
                ldsm_x4(ah[mt], smem_u32(sAh + row*SAPAD + kc));
                ldsm_x4(al[mt], smem_u32(sAl + row*SAPAD + kc));
            }
            // merged B loads: one ldsm_x4 covers an nt pair
            #pragma unroll
            for (int ntp=0; ntp<2; ntp++){
                int row = wn*32 + ntp*16 + ((lane >> 4) & 1)*8 + (lane & 7);
                int kc  = ks*16 + ((lane >> 3) & 1)*8;
                unsigned r4[4];
                ldsm_x4(r4, smem_u32(sBh + row*SAPAD + kc));
                bh[ntp*2  ][0]=r4[0]; bh[ntp*2  ][1]=r4[1];
                bh[ntp*2+1][0]=r4[2]; bh[ntp*2+1][1]=r4[3];
                ldsm_x4(r4, smem_u32(sBl + row*SAPAD + kc));
                bl[ntp*2  ][0]=r4[0]; bl[ntp*2  ][1]=r4[1];
                bl[ntp*2+1][0]=r4[2]; bl[ntp*2+1][1]=r4[3];
            }
            #pragma unroll
            for (int mt=0;mt<2;mt++)
                #pragma unroll
                for (int nt=0;nt<4;nt++){
                    mma16816(acc[mt][nt], ah[mt], bh[nt]);
                    mma16816(acc[mt][nt], ah[mt], bl[nt]);
                    mma16816(acc[mt][nt], al[mt], bh[nt]);
                }
        }
        __syncthreads();
    }

    // ---- epilogue ----
    #pragma unroll
    for (int mt=0;mt<2;mt++){
        #pragma unroll
        for (int nt=0;nt<4;nt++){
            int col = bn + wn*32 + nt*8 + (lane & 3)*2;
            #pragma unroll
            for (int half=0; half<2; half++){
                int row = bm + wm*32 + mt*16 + (lane >> 2) + half*8;
                float v0 = acc[mt][nt][half*2+0];
                float v1 = acc[mt][nt][half*2+1];
                if (EPI != 4){ v0 += bias[col]; v1 += bias[col+1]; }
                if (EPI == 1){
                    v0 = (v0>=0.f)? v0+1.f : expf(v0);
                    v1 = (v1>=0.f)? v1+1.f : expf(v1);
                }
                if (EPI == 2){
                    v0 = fmaxf(v0, 0.f); v1 = fmaxf(v1, 0.f);
                    bf16 h0,l0,h1,l1; split_bf16(v0,h0,l0); split_bf16(v1,h1,l1);
                    bf162 ph; ph.x=h0; ph.y=h1;
                    bf162 pl; pl.x=l0; pl.y=l1;
                    size_t o = (size_t)row*Ntot + col;
                    *(bf162*)(Ch + o) = ph;
                    *(bf162*)(Cl + o) = pl;
                } else {
                    float2 o2; o2.x=v0; o2.y=v1;
                    *(float2*)(Cf + (size_t)row*Ntot + col) = o2;
                }
            }
        }
    }
}

template<int EPI>
__global__ void __launch_bounds__(256) bgemm_kernel(
    int K, int Ntot, int ksplit,
    const bf16* __restrict__ Ah, const bf16* __restrict__ Al,
    const bf16* __restrict__ Bh, const bf16* __restrict__ Bl,
    const float* __restrict__ bias,
    float* __restrict__ Cf, bf16* __restrict__ Ch, bf16* __restrict__ Cl, size_t cstride)
{
    int z = blockIdx.z;
    gemm_core<EPI>(K, Ntot, z*ksplit, (z+1)*ksplit, Ah, Al, Bh, Bl, bias,
                   Cf + (size_t)z*cstride, Ch, Cl);
}

__global__ void __launch_bounds__(256) qkv_bgemm(
    const bf16* __restrict__ xh, const bf16* __restrict__ xl,
    const bf16* __restrict__ wqh, const bf16* __restrict__ wql, const float* __restrict__ bq,
    const bf16* __restrict__ wkh, const bf16* __restrict__ wkl, const float* __restrict__ bk,
    const bf16* __restrict__ wvh, const bf16* __restrict__ wvl, const float* __restrict__ bv,
    float* __restrict__ q, float* __restrict__ k, float* __restrict__ v)
{
    int z = blockIdx.z;
    if (z == 0)      gemm_core<1>(DM, DM, 0, DM, xh, xl, wqh, wql, bq, q, nullptr, nullptr);
    else if (z == 1) gemm_core<1>(DM, DM, 0, DM, xh, xl, wkh, wkl, bk, k, nullptr, nullptr);
    else             gemm_core<0>(DM, DM, 0, DM, xh, xl, wvh, wvl, bv, v, nullptr, nullptr);
}

// ---------------- per-chunk K^T V state + K column sums (vectorized: 256 thr, 4 out/thr) ----------------
__global__ void __launch_bounds__(256) chunk_kv_kernel(const float* __restrict__ k,
                                                       const float* __restrict__ v)
{
    int c = blockIdx.x, bh = blockIdx.y;
    int b = bh >> 3, h = bh & 7;
    __shared__ float ks[CHUNK][DH];
    __shared__ float vs[CHUNK][DH];
    int t = threadIdx.x;
    int base = b*NTOK + c*CHUNK;
    for (int idx=t; idx<CHUNK*8; idx+=256){
        int row = idx >> 3, c4 = (idx & 7)*4;
        size_t g = (size_t)(base+row)*DM + h*DH + c4;
        *(float4*)&ks[row][c4] = *(const float4*)(k + g);
        *(float4*)&vs[row][c4] = *(const float4*)(v + g);
    }
    __syncthreads();
    int d = t >> 3, m0 = (t & 7)*4;
    float s0=0.f, s1=0.f, s2=0.f, s3=0.f;
    #pragma unroll 4
    for (int j=0;j<CHUNK;j++){
        float kv = ks[j][d];
        float4 vv = *(const float4*)&vs[j][m0];
        s0 = fmaf(kv, vv.x, s0);
        s1 = fmaf(kv, vv.y, s1);
        s2 = fmaf(kv, vv.z, s2);
        s3 = fmaf(kv, vv.w, s3);
    }
    float4 o4; o4.x=s0; o4.y=s1; o4.z=s2; o4.w=s3;
    *(float4*)(g_Sloc + ((size_t)bh*NCHUNK + c)*DH*DH + d*DH + m0) = o4;
    if (t < DH){
        float kssum = 0.f;
        #pragma unroll 8
        for (int j=0;j<CHUNK;j++) kssum += ks[j][t];
        g_kloc[((size_t)bh*NCHUNK + c)*DH + t] = kssum;
    }
}

// ---------------- attention output (CHUNK=64: 64 thr/block, vectorized loads) ----------------
__global__ void __launch_bounds__(64) attn_kernel(const float* __restrict__ q,
                                                  const float* __restrict__ k,
                                                  const float* __restrict__ v,
                                                  bf16* __restrict__ ah_out,
                                                  bf16* __restrict__ al_out)
{
    int c = blockIdx.x, bh = blockIdx.y;
    int b = bh >> 3, h = bh & 7;
    __shared__ float ks[CHUNK][DH];
    __shared__ float vs[CHUNK][DH];
    __shared__ float Ss[DH][DH];
    __shared__ float kss[DH];
    int t = threadIdx.x;               // row within chunk, 0..63
    int base = b*NTOK + c*CHUNK;
    for (int idx=t; idx<CHUNK*8; idx+=64){
        int row = idx >> 3, c4 = (idx & 7)*4;
        size_t g = (size_t)(base+row)*DM + h*DH + c4;
        *(float4*)&ks[row][c4] = *(const float4*)(k + g);
        *(float4*)&vs[row][c4] = *(const float4*)(v + g);
    }
    // exclusive prefix of chunk states, inline (c <= 23, L2-resident), float4
    for (int idx=t; idx<DH*DH/4; idx+=64){
        float4 s4 = make_float4(0.f,0.f,0.f,0.f);
        const float4* p = (const float4*)(g_Sloc + (size_t)bh*NCHUNK*DH*DH) + idx;
        for (int cc=0; cc<c; cc++){
            float4 w = p[cc*(DH*DH/4)];
            s4.x += w.x; s4.y += w.y; s4.z += w.z; s4.w += w.w;
        }
        ((float4*)&Ss[0][0])[idx] = s4;
    }
    if (t < DH){
        float s = 0.f;
        const float* p = g_kloc + (size_t)bh*NCHUNK*DH + t;
        for (int cc=0; cc<c; cc++) s += p[cc*DH];
        kss[t] = s;
    }
    __syncthreads();

    float qr[DH], num[DH];
    {
        const float4* qp = (const float4*)(q + (size_t)(base+t)*DM + h*DH);
        #pragma unroll
        for (int d4=0; d4<8; d4++){
            float4 w4 = qp[d4];
            qr[4*d4+0]=w4.x; qr[4*d4+1]=w4.y; qr[4*d4+2]=w4.z; qr[4*d4+3]=w4.w;
        }
    }
    #pragma unroll
    for (int m=0;m<DH;m++) num[m] = 0.f;
    float z = 0.f;

    #pragma unroll
    for (int d=0; d<DH; d++){
        float qa = qr[d];
        z = fmaf(qa, kss[d], z);
        #pragma unroll
        for (int m=0;m<DH;m++) num[m] = fmaf(qa, Ss[d][m], num[m]);
    }
    int jend = t | 31;                 // rows consecutive within warp -> uniform
    for (int j=0; j<=jend; j+=2){
        float aa0 = 0.f, aa1 = 0.f;
        #pragma unroll
        for (int d=0; d<DH; d++){
            aa0 = fmaf(qr[d], ks[j  ][d], aa0);
            aa1 = fmaf(qr[d], ks[j+1][d], aa1);
        }
        aa0 = (j   <= t) ? aa0 : 0.f;
        aa1 = (j+1 <= t) ? aa1 : 0.f;
        z += aa0 + aa1;
        #pragma unroll
        for (int m=0;m<DH;m++){
            float nm = fmaf(aa0, vs[j][m], num[m]);
            num[m] = fmaf(aa1, vs[j+1][m], nm);
        }
    }
    float inv = 1.f / (z + 1e-6f);
    size_t ob = (size_t)(base+t)*DM + h*DH;
    #pragma unroll
    for (int m=0;m<DH;m+=2){
        float v0 = num[m]*inv, v1 = num[m+1]*inv;
        bf16 h0,l0,h1,l1; split_bf16(v0,h0,l0); split_bf16(v1,h1,l1);
        bf162 ph; ph.x=h0; ph.y=h1;
        bf162 pl; pl.x=l0; pl.y=l1;
        *(bf162*)(ah_out + ob + m) = ph;
        *(bf162*)(al_out + ob + m) = pl;
    }
}

// ---------------- residual + split-K reduce + LayerNorm (fused, + bf16 split out) ----------------
__global__ void __launch_bounds__(256) ln_red_kernel(
    int np, const float* __restrict__ part, size_t pstride,
    const float* __restrict__ xin, const float* __restrict__ bias,
    const float* __restrict__ w, const float* __restrict__ b,
    float* __restrict__ out, bf16* __restrict__ oh, bf16* __restrict__ ol)
{
    __shared__ float red[8], red2[8];
    int r = blockIdx.x, t = threadIdx.x;
    size_t o = (size_t)r*DM + t;
    float v = xin[o] + bias[t];
    for (int i=0;i<np;i++) v += part[(size_t)i*pstride + o];
    float s = v, s2 = v*v;
    #pragma unroll
    for (int off=16;off;off>>=1){ s += __shfl_xor_sync(~0u,s,off); s2 += __shfl_xor_sync(~0u,s2,off); }
    int warp = t >> 5, lane = t & 31;
    if (lane == 0){ red[warp] = s; red2[warp] = s2; }
    __syncthreads();
    float S=0.f, S2=0.f;
    #pragma unroll
    for (int i=0;i<8;i++){ S += red[i]; S2 += red2[i]; }
    float mean = S * (1.f/DM);
    float var  = S2 * (1.f/DM) - mean*mean;
    float ov = (v - mean) * rsqrtf(var + 1e-5f) * w[t] + b[t];
    out[o] = ov;
    bf16 h, lo; split_bf16(ov, h, lo);
    oh[o] = h; ol[o] = lo;
}

// ---------------- head: mean / sigma ----------------
__global__ void __launch_bounds__(256) head_kernel(const float* __restrict__ x,
                                                   const float* __restrict__ mW, const float* __restrict__ mb,
                                                   const float* __restrict__ sW, const float* __restrict__ sb,
                                                   float* __restrict__ out)
{
    __shared__ float sx[DM];
    int r = blockIdx.x;
    int b = r / SFUT, s = r % SFUT;
    const float* xr = x + (size_t)(b*NTOK + SPAST + s)*DM;
    int t = threadIdx.x;
    sx[t] = xr[t];
    __syncthreads();
    int warp = t >> 5, lane = t & 31;
    float am = 0.f, as = 0.f;
    for (int kk=lane; kk<DM; kk+=32){
        float xv = sx[kk];
        am = fmaf(xv, mW[kk*8 + warp], am);
        as = fmaf(xv, sW[kk*8 + warp], as);
    }
    #pragma unroll
    for (int off=16;off;off>>=1){ am += __shfl_xor_sync(~0u,am,off); as += __shfl_xor_sync(~0u,as,off); }
    if (lane == 0){
        int o = r*8 + warp;
        out[o] = am + mb[warp];
        float sp = as + sb[warp];
        float spv = (sp > 20.f) ? sp : log1pf(expf(sp));
        out[BATCH*SFUT*8 + o] = 0.01f + 0.99f*spv;
    }
}

// ---------------- launch ----------------
extern "C" void kernel_launch(void* const* d_in, const int* in_sizes, int n_in,
                              void* d_out, int out_size)
{
    (void)in_sizes; (void)n_in; (void)out_size;
    const float* past_x   = (const float*)d_in[0];
    const float* past_y   = (const float*)d_in[1];
    const float* future_x = (const float*)d_in[2];
    const float* enc_W    = (const float*)d_in[3];
    const float* enc_b    = (const float*)d_in[4];
    const float* Wq  = (const float*)d_in[5];  const float* bq  = (const float*)d_in[6];
    const float* Wk  = (const float*)d_in[7];  const float* bk  = (const float*)d_in[8];
    const float* Wv  = (const float*)d_in[9];  const float* bv  = (const float*)d_in[10];
    const float* Wo  = (const float*)d_in[11]; const float* bo  = (const float*)d_in[12];
    const float* ln1w= (const float*)d_in[13]; const float* ln1b= (const float*)d_in[14];
    const float* W1  = (const float*)d_in[15]; const float* b1  = (const float*)d_in[16];
    const float* W2  = (const float*)d_in[17]; const float* b2  = (const float*)d_in[18];
    const float* ln2w= (const float*)d_in[19]; const float* ln2b= (const float*)d_in[20];
    const float* mW  = (const float*)d_in[21]; const float* mb  = (const float*)d_in[22];
    const float* sW  = (const float*)d_in[23]; const float* sb  = (const float*)d_in[24];

    float *x,*q,*k,*v,*part;
    bf16 *xh,*xl,*ah,*al,*hh,*hl;
    bf16 *wqh,*wql,*wkh,*wkl,*wvh,*wvl,*woh,*wol,*w1h,*w1l,*w2h,*w2l;
    cudaGetSymbolAddress((void**)&x,   g_x);
    cudaGetSymbolAddress((void**)&q,   g_qb);
    cudaGetSymbolAddress((void**)&k,   g_kb);
    cudaGetSymbolAddress((void**)&v,   g_vb);
    cudaGetSymbolAddress((void**)&part,g_part);
    cudaGetSymbolAddress((void**)&xh,  g_xh);  cudaGetSymbolAddress((void**)&xl, g_xl);
    cudaGetSymbolAddress((void**)&ah,  g_ah);  cudaGetSymbolAddress((void**)&al, g_al);
    cudaGetSymbolAddress((void**)&hh,  g_hh);  cudaGetSymbolAddress((void**)&hl, g_hl);
    cudaGetSymbolAddress((void**)&wqh, g_wqh); cudaGetSymbolAddress((void**)&wql, g_wql);
    cudaGetSymbolAddress((void**)&wkh, g_wkh); cudaGetSymbolAddress((void**)&wkl, g_wkl);
    cudaGetSymbolAddress((void**)&wvh, g_wvh); cudaGetSymbolAddress((void**)&wvl, g_wvl);
    cudaGetSymbolAddress((void**)&woh, g_woh); cudaGetSymbolAddress((void**)&wol, g_wol);
    cudaGetSymbolAddress((void**)&w1h, g_w1h); cudaGetSymbolAddress((void**)&w1l, g_w1l);
    cudaGetSymbolAddress((void**)&w2h, g_w2h); cudaGetSymbolAddress((void**)&w2l, g_w2l);

    cudaFuncSetAttribute(qkv_bgemm,       cudaFuncAttributeMaxDynamicSharedMemorySize, GSMEM);
    cudaFuncSetAttribute(bgemm_kernel<2>, cudaFuncAttributeMaxDynamicSharedMemorySize, GSMEM);
    cudaFuncSetAttribute(bgemm_kernel<4>, cudaFuncAttributeMaxDynamicSharedMemorySize, GSMEM);

    // fused weight transpose + split (ONE launch; inputs constant -> deterministic)
    {
        ConvArgs ca;
        ca.W[0]=Wq;  ca.Oh[0]=wqh; ca.Ol[0]=wql;
        ca.W[1]=Wk;  ca.Oh[1]=wkh; ca.Ol[1]=wkl;
        ca.W[2]=Wv;  ca.Oh[2]=wvh; ca.Ol[2]=wvl;
        ca.W[3]=Wo;  ca.Oh[3]=woh; ca.Ol[3]=wol;
        ca.W[4]=W1;  ca.Oh[4]=w1h; ca.Ol[4]=w1l;
        ca.W[5]=W2;  ca.Oh[5]=w2h; ca.Ol[5]=w2l;
        convw_all<<<CONV_BLOCKS, dim3(32,8)>>>(ca);
    }

    embed_kernel<<<NROWS, 256>>>(past_x, past_y, future_x, enc_W, enc_b, x, xh, xl);

    dim3 gQKV(DM/BN,  NROWS/BM, 3);    // 4 x 48 x 3
    dim3 gWo (DM/BN,  NROWS/BM, 2);    // split-K 2
    dim3 gFF (DFF/BN, NROWS/BM, 1);    // 32 x 48
    dim3 gW2 (DM/BN,  NROWS/BM, 4);    // split-K 4
    dim3 gA  (NCHUNK, NBH);            // 24 x 32 = 768 blocks

    const size_t PS = (size_t)NROWS*DM;

    for (int i=0;i<NLAYERS;i++){
        const size_t wo4 = (size_t)i*DM*DM;
        const size_t wo1 = (size_t)i*DM*DFF;

        qkv_bgemm<<<gQKV, 256, GSMEM>>>(xh, xl,
            wqh+wo4, wql+wo4, bq+i*DM,
            wkh+wo4, wkl+wo4, bk+i*DM,
            wvh+wo4, wvl+wo4, bv+i*DM,
            q, k, v);

        chunk_kv_kernel<<<gA, 256>>>(k, v);
        attn_kernel<<<gA, 64>>>(q, k, v, ah, al);

        // Wo: split-K=2 raw partials, then fused residual+reduce+LN -> x (+split)
        bgemm_kernel<4><<<gWo, 256, GSMEM>>>(DM, DM, DM/2, ah, al,
            woh+wo4, wol+wo4, nullptr, part, nullptr, nullptr, PS);
        ln_red_kernel<<<NROWS, 256>>>(2, part, PS, x, bo+i*DM, ln1w+i*DM, ln1b+i*DM, x, xh, xl);

        // FFN
        bgemm_kernel<2><<<gFF, 256, GSMEM>>>(DM, DFF, DM, xh, xl,
            w1h+wo1, w1l+wo1, b1+i*DFF, nullptr, hh, hl, 0);
        bgemm_kernel<4><<<gW2, 256, GSMEM>>>(DFF, DM, DFF/4, hh, hl,
            w2h+wo1, w2l+wo1, nullptr, part, nullptr, nullptr, PS);
        ln_red_kernel<<<NROWS, 256>>>(4, part, PS, x, b2+i*DM, ln2w+i*DM, ln2b+i*DM, x, xh, xl);
    }

    head_kernel<<<BATCH*SFUT, 256>>>(x, mW, mb, sW, sb, (float*)d_out);
}